// round 11
// baseline (speedup 1.0000x reference)
#include <cuda_runtime.h>

#define NTOK 4096
#define NP1  4097
#define THREADS 512

__device__ __forceinline__ float comp(const float* __restrict__ buf, int off, int j,
                                      int cnt, float eos, float pad)
{ return j < cnt ? buf[j + off] : (j == cnt ? eos : pad); }

// Write one row of NP1 floats: buf[off..off+cnt) then EOS then PAD.
// (base+off+h) is 0 mod 4 -> aligned LDS.128 in the hot loop, no converts.
__device__ __forceinline__ void write_row(float* __restrict__ dst,
                                          const float* __restrict__ buf, int off,
                                          int cnt, float eos, float pad,
                                          int tid, int h)
{
    if (tid < h) dst[tid] = comp(buf, off, tid, cnt, eos, pad);
    const int nv = (NP1 - h) >> 2;
    const float4* __restrict__ b4 = (const float4*)(buf + off + h);
    float4* __restrict__ d4 = (float4*)(dst + h);

    int i_c = (cnt >= h) ? ((cnt - h) >> 2) : 0;  if (i_c > nv) i_c = nv;
    int i_p = (cnt >= h) ? (i_c + 1) : 0;         if (i_p > nv) i_p = nv;

#pragma unroll 2
    for (int i = tid; i < i_c; i += THREADS) d4[i] = b4[i];      // content chunks
    if (tid == 0) {                                              // boundary chunk
        for (int i = i_c; i < i_p; i++) {
            const int s = h + i * 4;
            d4[i] = make_float4(comp(buf, off, s,     cnt, eos, pad),
                                comp(buf, off, s + 1, cnt, eos, pad),
                                comp(buf, off, s + 2, cnt, eos, pad),
                                comp(buf, off, s + 3, cnt, eos, pad));
        }
    }
    const float4 pp = make_float4(pad, pad, pad, pad);
#pragma unroll 2
    for (int i = i_p + tid; i < nv; i += THREADS) d4[i] = pp;    // pad chunks
    const int base = h + nv * 4;
    for (int j = base + tid; j < NP1; j += THREADS)              // tail (<=1 elem)
        dst[j] = comp(buf, off, j, cnt, eos, pad);
}

__device__ __forceinline__ void write_const_row(float* __restrict__ dst, float val,
                                                int tid, int h)
{
    if (tid < h) dst[tid] = val;
    const int nv = (NP1 - h) >> 2;
    float4* __restrict__ d4 = (float4*)(dst + h);
    const float4 w = make_float4(val, val, val, val);
#pragma unroll 2
    for (int i = tid; i < nv; i += THREADS) d4[i] = w;
    const int base = h + nv * 4;
    for (int j = base + tid; j < NP1; j += THREADS) dst[j] = val;
}

__global__ __launch_bounds__(THREADS)
void permute_kernel(const int* __restrict__ indices,
                    const int* __restrict__ grains,
                    float* __restrict__ out,
                    long long M)
{
    __shared__ float sb[4108];        // 3 runtime-packed stream regions (16.4 KB)
    __shared__ unsigned wsum[16];

    // 1D grid, roles interleaved so each SM's resident set mixes all roles:
    // role 2 CTAs (pure const stores) keep the write port busy while role 0/1
    // CTAs sit in their load+scan prologue.
    const int bid  = blockIdx.x;
    const int role = bid % 3;         // 0 = content rows, 1 = position rows, 2 = const
    const int b    = bid / 3;
    const int tid  = threadIdx.x;
    const int lane = tid & 31;
    const int warp = tid >> 5;

    const long long rb = (long long)b * NP1;
    const int h = (int)((0u - ((unsigned)(size_t)(out + rb) >> 2)) & 3u);

    // ---- role 2: pure constant stores, no input dependency ----
    if (role == 2) {
        write_const_row(out + 6 * M + rb, 0.0f, tid, h);
        write_const_row(out + 7 * M + rb, 1.0f, tid, h);
        write_const_row(out + 8 * M + rb, 2.0f, tid, h);
        return;
    }

    // ---- issue input loads ----
    const int4* gv = (const int4*)(grains + (long long)b * NTOK);
    int4 ga = gv[tid * 2], gb = gv[tid * 2 + 1];
    int v[8] = {0,0,0,0,0,0,0,0};
    if (role == 0) {
        const int4* iv = (const int4*)(indices + (long long)b * NTOK);
        int4 ia = iv[tid * 2], ib = iv[tid * 2 + 1];
        v[0]=ia.x; v[1]=ia.y; v[2]=ia.z; v[3]=ia.w;
        v[4]=ib.x; v[5]=ib.y; v[6]=ib.z; v[7]=ib.w;
    }
    int g[8] = {ga.x, ga.y, ga.z, ga.w, gb.x, gb.y, gb.z, gb.w};

    // ---- packed dual-field block scan (c0 low 16, c1 high 16) ----
    unsigned packed = 0;
#pragma unroll
    for (int i = 0; i < 8; i++)
        packed += (g[i] == 0) ? 1u : ((g[i] == 1) ? 0x10000u : 0u);
    unsigned p = packed;
#pragma unroll
    for (int d = 1; d < 32; d <<= 1) {
        unsigned t = __shfl_up_sync(0xffffffffu, p, d);
        if (lane >= d) p += t;
    }
    if (lane == 31) wsum[warp] = p;
    __syncthreads();
    if (warp == 0 && lane < 16) {
        unsigned x = wsum[lane];
#pragma unroll
        for (int d = 1; d < 16; d <<= 1) {
            unsigned t = __shfl_up_sync(0x0000ffffu, x, d);
            if (lane >= d) x += t;
        }
        wsum[lane] = x;
    }
    __syncthreads();
    const unsigned excl  = p - packed + (warp ? wsum[warp - 1] : 0u);
    const unsigned total = wsum[15];

    const int e0 = (int)(excl & 0xFFFFu), e1 = (int)(excl >> 16);
    const int c0 = (int)(total & 0xFFFFu), c1 = (int)(total >> 16);
    const int c2 = NTOK - c0 - c1;

    // ---- stream region bases (0 mod 4 so writer chunks stay 16B aligned) ----
    const int off   = (4 - h) & 3;
    const int base1 = (c0 + 3) & ~3;
    const int base2 = base1 + ((c1 + 3) & ~3);

    // ---- stable scatter (floats, converted once) ----
    int q0 = off + e0;
    int q1 = base1 + off + e1;
    int q2 = base2 + off + (tid * 8 - e0 - e1);
    const int t0 = tid * 8;
#pragma unroll
    for (int i = 0; i < 8; i++) {
        const int gi = g[i];
        const float w = (role == 0) ? (float)v[i] : (float)(t0 + i);
        if (gi == 0)      sb[q0++] = w;
        else if (gi == 1) sb[q1++] = w;
        else              sb[q2++] = w;
    }
    __syncthreads();

    // ---- write this role's 3 rows ----
    if (role == 0) {
        write_row(out + 0 * M + rb, sb,         off, c0, 1025.f, 1024.f, tid, h);
        write_row(out + 1 * M + rb, sb + base1, off, c1, 1025.f, 1024.f, tid, h);
        write_row(out + 2 * M + rb, sb + base2, off, c2, 1025.f, 1024.f, tid, h);
    } else {
        write_row(out + 3 * M + rb, sb,         off, c0,  129.f,  128.f, tid, h);
        write_row(out + 4 * M + rb, sb + base1, off, c1,  257.f,  256.f, tid, h);
        write_row(out + 5 * M + rb, sb + base2, off, c2, 1025.f, 1024.f, tid, h);
    }
}

extern "C" void kernel_launch(void* const* d_in, const int* in_sizes, int n_in,
                              void* d_out, int out_size)
{
    const int* indices = (const int*)d_in[0];
    const int* grains  = (const int*)d_in[1];
    const int rows = in_sizes[0] / NTOK;            // 512
    const long long M = (long long)out_size / 9;
    permute_kernel<<<rows * 3, THREADS>>>(indices, grains, (float*)d_out, M);
}

// round 13
// speedup vs baseline: 1.5217x; 1.5217x over previous
#include <cuda_runtime.h>

#define NTOK 4096
#define NP1  4097
#define THREADS 512

__device__ __forceinline__ float comp(const float* __restrict__ buf, int off, int j,
                                      int cnt, float eos, float pad)
{ return j < cnt ? buf[j + off] : (j == cnt ? eos : pad); }

// Write one row of NP1 floats: buf[off..off+cnt) then EOS then PAD.
// (base+off+h) is 0 mod 4 -> aligned LDS.128 in the hot loop, no converts.
__device__ __forceinline__ void write_row(float* __restrict__ dst,
                                          const float* __restrict__ buf, int off,
                                          int cnt, float eos, float pad,
                                          int tid, int h)
{
    if (tid < h) dst[tid] = comp(buf, off, tid, cnt, eos, pad);
    const int nv = (NP1 - h) >> 2;
    const float4* __restrict__ b4 = (const float4*)(buf + off + h);
    float4* __restrict__ d4 = (float4*)(dst + h);

    int i_c = (cnt >= h) ? ((cnt - h) >> 2) : 0;  if (i_c > nv) i_c = nv;
    int i_p = (cnt >= h) ? (i_c + 1) : 0;         if (i_p > nv) i_p = nv;

#pragma unroll 2
    for (int i = tid; i < i_c; i += THREADS) d4[i] = b4[i];      // content chunks
    if (tid == 0) {                                              // boundary chunk
        for (int i = i_c; i < i_p; i++) {
            const int s = h + i * 4;
            d4[i] = make_float4(comp(buf, off, s,     cnt, eos, pad),
                                comp(buf, off, s + 1, cnt, eos, pad),
                                comp(buf, off, s + 2, cnt, eos, pad),
                                comp(buf, off, s + 3, cnt, eos, pad));
        }
    }
    const float4 pp = make_float4(pad, pad, pad, pad);
#pragma unroll 2
    for (int i = i_p + tid; i < nv; i += THREADS) d4[i] = pp;    // pad chunks
    const int base = h + nv * 4;
    for (int j = base + tid; j < NP1; j += THREADS)              // tail (<=1 elem)
        dst[j] = comp(buf, off, j, cnt, eos, pad);
}

__device__ __forceinline__ void write_const_row(float* __restrict__ dst, float val,
                                                int tid, int h)
{
    if (tid < h) dst[tid] = val;
    const int nv = (NP1 - h) >> 2;
    float4* __restrict__ d4 = (float4*)(dst + h);
    const float4 w = make_float4(val, val, val, val);
#pragma unroll 2
    for (int i = tid; i < nv; i += THREADS) d4[i] = w;
    const int base = h + nv * 4;
    for (int j = base + tid; j < NP1; j += THREADS) dst[j] = val;
}

__global__ __launch_bounds__(THREADS)
void permute_kernel(const int* __restrict__ indices,
                    const int* __restrict__ grains,
                    float* __restrict__ out,
                    long long M)
{
    __shared__ float sb[4108];        // 3 runtime-packed stream regions (16.4 KB)
    __shared__ unsigned wsum[16];

    const int b    = blockIdx.x;
    const int role = blockIdx.y;      // 0 = content rows, 1 = position rows
    const int tid  = threadIdx.x;
    const int lane = tid & 31;
    const int warp = tid >> 5;

    // ---- issue input loads first ----
    const int4* gv = (const int4*)(grains + (long long)b * NTOK);
    int4 ga = gv[tid * 2], gb = gv[tid * 2 + 1];
    int v[8] = {0,0,0,0,0,0,0,0};
    if (role == 0) {
        const int4* iv = (const int4*)(indices + (long long)b * NTOK);
        int4 ia = iv[tid * 2], ib = iv[tid * 2 + 1];
        v[0]=ia.x; v[1]=ia.y; v[2]=ia.z; v[3]=ia.w;
        v[4]=ib.x; v[5]=ib.y; v[6]=ib.z; v[7]=ib.w;
    }
    int g[8] = {ga.x, ga.y, ga.z, ga.w, gb.x, gb.y, gb.z, gb.w};

    const long long rb = (long long)b * NP1;
    const int h = (int)((0u - ((unsigned)(size_t)(out + rb) >> 2)) & 3u);

    // ---- constant rows first: pure stores, hide load/scan latency ----
    if (role == 0) {
        write_const_row(out + 6 * M + rb, 0.0f, tid, h);
        float* __restrict__ r7 = out + 7 * M + rb;
        for (int j = tid; j < 2048; j += THREADS) r7[j] = 1.0f;
    } else {
        write_const_row(out + 8 * M + rb, 2.0f, tid, h);
        float* __restrict__ r7 = out + 7 * M + rb;
        for (int j = 2048 + tid; j < NP1; j += THREADS) r7[j] = 1.0f;
    }

    // ---- packed dual-field block scan (c0 low 16, c1 high 16) ----
    unsigned packed = 0;
#pragma unroll
    for (int i = 0; i < 8; i++)
        packed += (g[i] == 0) ? 1u : ((g[i] == 1) ? 0x10000u : 0u);
    unsigned p = packed;
#pragma unroll
    for (int d = 1; d < 32; d <<= 1) {
        unsigned t = __shfl_up_sync(0xffffffffu, p, d);
        if (lane >= d) p += t;
    }
    if (lane == 31) wsum[warp] = p;
    __syncthreads();                  // single barrier: every thread folds wsum itself

    unsigned pref = 0, total = 0;
#pragma unroll
    for (int wdx = 0; wdx < 16; wdx++) {
        const unsigned ws = wsum[wdx];
        total += ws;
        if (wdx < warp) pref += ws;
    }
    const unsigned excl = p - packed + pref;

    const int e0 = (int)(excl & 0xFFFFu), e1 = (int)(excl >> 16);
    const int c0 = (int)(total & 0xFFFFu), c1 = (int)(total >> 16);
    const int c2 = NTOK - c0 - c1;

    // ---- stream region bases (0 mod 4 so writer chunks stay 16B aligned) ----
    const int off   = (4 - h) & 3;
    const int base1 = (c0 + 3) & ~3;
    const int base2 = base1 + ((c1 + 3) & ~3);

    // ---- stable scatter (floats, converted once) ----
    int q0 = off + e0;
    int q1 = base1 + off + e1;
    int q2 = base2 + off + (tid * 8 - e0 - e1);
    const int t0 = tid * 8;
#pragma unroll
    for (int i = 0; i < 8; i++) {
        const int gi = g[i];
        const float w = (role == 0) ? (float)v[i] : (float)(t0 + i);
        if (gi == 0)      sb[q0++] = w;
        else if (gi == 1) sb[q1++] = w;
        else              sb[q2++] = w;
    }
    __syncthreads();

    // ---- write this role's 3 rows ----
    if (role == 0) {
        write_row(out + 0 * M + rb, sb,         off, c0, 1025.f, 1024.f, tid, h);
        write_row(out + 1 * M + rb, sb + base1, off, c1, 1025.f, 1024.f, tid, h);
        write_row(out + 2 * M + rb, sb + base2, off, c2, 1025.f, 1024.f, tid, h);
    } else {
        write_row(out + 3 * M + rb, sb,         off, c0,  129.f,  128.f, tid, h);
        write_row(out + 4 * M + rb, sb + base1, off, c1,  257.f,  256.f, tid, h);
        write_row(out + 5 * M + rb, sb + base2, off, c2, 1025.f, 1024.f, tid, h);
    }
}

extern "C" void kernel_launch(void* const* d_in, const int* in_sizes, int n_in,
                              void* d_out, int out_size)
{
    const int* indices = (const int*)d_in[0];
    const int* grains  = (const int*)d_in[1];
    const int rows = in_sizes[0] / NTOK;            // 512
    const long long M = (long long)out_size / 9;
    dim3 grid(rows, 2);
    permute_kernel<<<grid, THREADS>>>(indices, grains, (float*)d_out, M);
}

// round 16
// speedup vs baseline: 1.5776x; 1.0367x over previous
#include <cuda_runtime.h>

#define NTOK 4096
#define NP1  4097
#define THREADS 256
#define IPT 16                         // tokens per thread
#define NWARP (THREADS / 32)

__device__ __forceinline__ float comp(const float* __restrict__ buf, int off, int j,
                                      int cnt, float eos, float pad)
{ return j < cnt ? buf[j + off] : (j == cnt ? eos : pad); }

// Write one row of NP1 floats: buf[off..off+cnt) then EOS then PAD.
// (base+off+h) is 0 mod 4 -> aligned LDS.128 in the hot loop, no converts.
__device__ __forceinline__ void write_row(float* __restrict__ dst,
                                          const float* __restrict__ buf, int off,
                                          int cnt, float eos, float pad,
                                          int tid, int h)
{
    if (tid < h) dst[tid] = comp(buf, off, tid, cnt, eos, pad);
    const int nv = (NP1 - h) >> 2;
    const float4* __restrict__ b4 = (const float4*)(buf + off + h);
    float4* __restrict__ d4 = (float4*)(dst + h);

    int i_c = (cnt >= h) ? ((cnt - h) >> 2) : 0;  if (i_c > nv) i_c = nv;
    int i_p = (cnt >= h) ? (i_c + 1) : 0;         if (i_p > nv) i_p = nv;

#pragma unroll 2
    for (int i = tid; i < i_c; i += THREADS) d4[i] = b4[i];      // content chunks
    if (tid == 0) {                                              // boundary chunk
        for (int i = i_c; i < i_p; i++) {
            const int s = h + i * 4;
            d4[i] = make_float4(comp(buf, off, s,     cnt, eos, pad),
                                comp(buf, off, s + 1, cnt, eos, pad),
                                comp(buf, off, s + 2, cnt, eos, pad),
                                comp(buf, off, s + 3, cnt, eos, pad));
        }
    }
    const float4 pp = make_float4(pad, pad, pad, pad);
#pragma unroll 2
    for (int i = i_p + tid; i < nv; i += THREADS) d4[i] = pp;    // pad chunks
    const int base = h + nv * 4;
    for (int j = base + tid; j < NP1; j += THREADS)              // tail (<=1 elem)
        dst[j] = comp(buf, off, j, cnt, eos, pad);
}

__device__ __forceinline__ void write_const_row(float* __restrict__ dst, float val,
                                                int tid, int h)
{
    if (tid < h) dst[tid] = val;
    const int nv = (NP1 - h) >> 2;
    float4* __restrict__ d4 = (float4*)(dst + h);
    const float4 w = make_float4(val, val, val, val);
#pragma unroll 2
    for (int i = tid; i < nv; i += THREADS) d4[i] = w;
    const int base = h + nv * 4;
    for (int j = base + tid; j < NP1; j += THREADS) dst[j] = val;
}

__global__ __launch_bounds__(THREADS)
void permute_kernel(const int* __restrict__ indices,
                    const int* __restrict__ grains,
                    float* __restrict__ out,
                    long long M)
{
    __shared__ float sb[4108];        // 3 runtime-packed stream regions (16.4 KB)
    __shared__ unsigned wsum[NWARP];

    const int b    = blockIdx.x;
    const int role = blockIdx.y;      // 0 = content rows, 1 = position rows
    const int tid  = threadIdx.x;
    const int lane = tid & 31;
    const int warp = tid >> 5;

    // ---- issue input loads first (16 tokens per thread, contiguous chunk) ----
    const int4* gv = (const int4*)(grains + (long long)b * NTOK);
    int4 gq[4];
#pragma unroll
    for (int k = 0; k < 4; k++) gq[k] = gv[tid * 4 + k];
    int v[IPT];
#pragma unroll
    for (int i = 0; i < IPT; i++) v[i] = 0;
    if (role == 0) {
        const int4* iv = (const int4*)(indices + (long long)b * NTOK);
#pragma unroll
        for (int k = 0; k < 4; k++) {
            int4 t = iv[tid * 4 + k];
            v[k*4+0] = t.x; v[k*4+1] = t.y; v[k*4+2] = t.z; v[k*4+3] = t.w;
        }
    }
    int g[IPT];
#pragma unroll
    for (int k = 0; k < 4; k++) {
        g[k*4+0] = gq[k].x; g[k*4+1] = gq[k].y; g[k*4+2] = gq[k].z; g[k*4+3] = gq[k].w;
    }

    const long long rb = (long long)b * NP1;
    const int h = (int)((0u - ((unsigned)(size_t)(out + rb) >> 2)) & 3u);

    // ---- constant rows first: pure stores, hide load/scan latency ----
    if (role == 0) {
        write_const_row(out + 6 * M + rb, 0.0f, tid, h);
        float* __restrict__ r7 = out + 7 * M + rb;
        for (int j = tid; j < 2048; j += THREADS) r7[j] = 1.0f;
    } else {
        write_const_row(out + 8 * M + rb, 2.0f, tid, h);
        float* __restrict__ r7 = out + 7 * M + rb;
        for (int j = 2048 + tid; j < NP1; j += THREADS) r7[j] = 1.0f;
    }

    // ---- packed dual-field block scan (c0 low 16, c1 high 16) ----
    unsigned packed = 0;
#pragma unroll
    for (int i = 0; i < IPT; i++)
        packed += (g[i] == 0) ? 1u : ((g[i] == 1) ? 0x10000u : 0u);
    unsigned p = packed;
#pragma unroll
    for (int d = 1; d < 32; d <<= 1) {
        unsigned t = __shfl_up_sync(0xffffffffu, p, d);
        if (lane >= d) p += t;
    }
    if (lane == 31) wsum[warp] = p;
    __syncthreads();                  // single barrier: every thread folds wsum

    unsigned pref = 0, total = 0;
#pragma unroll
    for (int wdx = 0; wdx < NWARP; wdx++) {
        const unsigned ws = wsum[wdx];
        total += ws;
        if (wdx < warp) pref += ws;
    }
    const unsigned excl = p - packed + pref;

    const int e0 = (int)(excl & 0xFFFFu), e1 = (int)(excl >> 16);
    const int c0 = (int)(total & 0xFFFFu), c1 = (int)(total >> 16);
    const int c2 = NTOK - c0 - c1;

    // ---- stream region bases (0 mod 4 so writer chunks stay 16B aligned) ----
    const int off   = (4 - h) & 3;
    const int base1 = (c0 + 3) & ~3;
    const int base2 = base1 + ((c1 + 3) & ~3);

    // ---- stable scatter (floats, converted once) ----
    int q0 = off + e0;
    int q1 = base1 + off + e1;
    int q2 = base2 + off + (tid * IPT - e0 - e1);
    const int t0 = tid * IPT;
#pragma unroll
    for (int i = 0; i < IPT; i++) {
        const int gi = g[i];
        const float w = (role == 0) ? (float)v[i] : (float)(t0 + i);
        if (gi == 0)      sb[q0++] = w;
        else if (gi == 1) sb[q1++] = w;
        else              sb[q2++] = w;
    }
    __syncthreads();

    // ---- write this role's 3 rows ----
    if (role == 0) {
        write_row(out + 0 * M + rb, sb,         off, c0, 1025.f, 1024.f, tid, h);
        write_row(out + 1 * M + rb, sb + base1, off, c1, 1025.f, 1024.f, tid, h);
        write_row(out + 2 * M + rb, sb + base2, off, c2, 1025.f, 1024.f, tid, h);
    } else {
        write_row(out + 3 * M + rb, sb,         off, c0,  129.f,  128.f, tid, h);
        write_row(out + 4 * M + rb, sb + base1, off, c1,  257.f,  256.f, tid, h);
        write_row(out + 5 * M + rb, sb + base2, off, c2, 1025.f, 1024.f, tid, h);
    }
}

extern "C" void kernel_launch(void* const* d_in, const int* in_sizes, int n_in,
                              void* d_out, int out_size)
{
    const int* indices = (const int*)d_in[0];
    const int* grains  = (const int*)d_in[1];
    const int rows = in_sizes[0] / NTOK;            // 512
    const long long M = (long long)out_size / 9;
    dim3 grid(rows, 2);
    permute_kernel<<<grid, THREADS>>>(indices, grains, (float*)d_out, M);
}